// round 1
// baseline (speedup 1.0000x reference)
#include <cuda_runtime.h>
#include <math_constants.h>

// Problem constants
#define BB 128
#define NN 16
#define MM 32
#define DOBS 128
#define DOUT 128
#define DOA 136
#define DAV 128
#define DHID 64
#define NACT 8

struct Smem {
    float oa[NN][136];    // states | actions  (2176)
    float pol[NN][8];     // policies          (128)
    float oao[MM][136];   // states_o | actions_o (4352)
    float kk[NN][128];
    float qq[NN][128];
    float qo[NN][128];
    float t[NN][128];     // states @ Wv[:128]
    float avact[NN][128];
    float delta[NN][128]; // av_pol, then av_pol - av_act
    float ko[MM][128];
    float avo[MM][128];
    float w[NN][NN];      // attention weights
    float wo[NN][MM];     // other attention weights
    float base_[NN][128]; // weight @ av_act
    float wavo[NN][128];  // weight_o @ av_o
    float u[NN][64];
    float v[NN][64];
    float w2[64];
};

// Generic small GEMM: out[R,C] = act( A[R,K](lda) @ W[K,C] (+ add_src) )
// 256 threads. C must divide 256; R must divide by (256/C).
// A in shared memory (float4-aligned rows, K%4==0), W in global/shared.
template<int R, int K, int C, int ACT, bool ADD>
__device__ __forceinline__ void gemm_rc(const float* __restrict__ A, int lda,
                                        const float* __restrict__ W,
                                        const float* __restrict__ add_src,
                                        float* __restrict__ out) {
    constexpr int G  = 256 / C;   // column groups
    constexpr int RB = R / G;     // rows per thread
    const int tid = threadIdx.x;
    const int c   = tid % C;
    const int r0  = (tid / C) * RB;

    float acc[RB];
#pragma unroll
    for (int i = 0; i < RB; i++) acc[i] = 0.f;

#pragma unroll 2
    for (int k = 0; k < K; k += 4) {
        const float w0 = W[(k + 0) * C + c];
        const float w1 = W[(k + 1) * C + c];
        const float w2 = W[(k + 2) * C + c];
        const float w3 = W[(k + 3) * C + c];
#pragma unroll
        for (int i = 0; i < RB; i++) {
            const float4 a = *reinterpret_cast<const float4*>(A + (r0 + i) * lda + k);
            acc[i] = fmaf(a.x, w0, acc[i]);
            acc[i] = fmaf(a.y, w1, acc[i]);
            acc[i] = fmaf(a.z, w2, acc[i]);
            acc[i] = fmaf(a.w, w3, acc[i]);
        }
    }
#pragma unroll
    for (int i = 0; i < RB; i++) {
        float x = acc[i];
        if (ADD) x += add_src[(r0 + i) * C + c];
        if (ACT == 1) x = tanhf(x);
        out[(r0 + i) * C + c] = x;
    }
}

__global__ __launch_bounds__(256, 1)
void critic_kernel(const float* __restrict__ states,
                   const float* __restrict__ policies,
                   const float* __restrict__ actions,
                   const float* __restrict__ states_o,
                   const float* __restrict__ actions_o,
                   const float* __restrict__ Wk,  const float* __restrict__ Wq,
                   const float* __restrict__ Wv,  const float* __restrict__ Wko,
                   const float* __restrict__ Wqo, const float* __restrict__ Wvo,
                   const float* __restrict__ W1,  const float* __restrict__ W2,
                   float* __restrict__ out_value,
                   float* __restrict__ out_w,
                   float* __restrict__ out_wo)
{
    extern __shared__ unsigned char smem_raw[];
    Smem& sm = *reinterpret_cast<Smem*>(smem_raw);

    const int b   = blockIdx.x;
    const int tid = threadIdx.x;

    // ---------------- Load phase ----------------
    {
        const float4* Sb = reinterpret_cast<const float4*>(states + (size_t)b * NN * DOBS);
        for (int idx = tid; idx < NN * 32; idx += 256) {
            int r = idx >> 5, c4 = idx & 31;
            *reinterpret_cast<float4*>(&sm.oa[r][c4 * 4]) = Sb[idx];
        }
        const float* Ab = actions + (size_t)b * NN * NACT;
        const float* Pb = policies + (size_t)b * NN * NACT;
        for (int idx = tid; idx < NN * NACT; idx += 256) {
            int r = idx >> 3, c = idx & 7;
            sm.oa[r][128 + c] = Ab[idx];
            sm.pol[r][c]      = Pb[idx];
        }
        const float4* SOb = reinterpret_cast<const float4*>(states_o + (size_t)b * MM * DOBS);
        for (int idx = tid; idx < MM * 32; idx += 256) {
            int r = idx >> 5, c4 = idx & 31;
            *reinterpret_cast<float4*>(&sm.oao[r][c4 * 4]) = SOb[idx];
        }
        const float* AOb = actions_o + (size_t)b * MM * NACT;
        for (int idx = tid; idx < MM * NACT; idx += 256) {
            int r = idx >> 3, c = idx & 7;
            sm.oao[r][128 + c] = AOb[idx];
        }
        if (tid < 64) sm.w2[tid] = W2[tid];
    }
    __syncthreads();

    // ---------------- Projection GEMMs ----------------
    gemm_rc<NN, 128, 128, 0, false>(&sm.oa[0][0],  136, Wk,  nullptr, &sm.kk[0][0]);
    gemm_rc<NN, 128, 128, 0, false>(&sm.oa[0][0],  136, Wq,  nullptr, &sm.qq[0][0]);
    gemm_rc<NN, 128, 128, 0, false>(&sm.oa[0][0],  136, Wqo, nullptr, &sm.qo[0][0]);
    gemm_rc<NN, 128, 128, 0, false>(&sm.oa[0][0],  136, Wv,  nullptr, &sm.t[0][0]);
    // av_act = tanh(t + actions @ Wv[128:]) ; av_pol = tanh(t + policies @ Wv[128:])
    gemm_rc<NN, 8, 128, 1, true>(&sm.oa[0][128], 136, Wv + 128 * 128, &sm.t[0][0], &sm.avact[0][0]);
    gemm_rc<NN, 8, 128, 1, true>(&sm.pol[0][0],    8, Wv + 128 * 128, &sm.t[0][0], &sm.delta[0][0]);
    gemm_rc<MM, 128, 128, 0, false>(&sm.oao[0][0], 136, Wko, nullptr, &sm.ko[0][0]);
    gemm_rc<MM, 136, 128, 1, false>(&sm.oao[0][0], 136, Wvo, nullptr, &sm.avo[0][0]);
    __syncthreads();

    // delta = av_pol - av_act
    {
        float* d = &sm.delta[0][0];
        const float* a = &sm.avact[0][0];
        for (int idx = tid; idx < NN * 128; idx += 256) d[idx] -= a[idx];
    }

    // ---------------- Attention scores ----------------
    const float scale = 0.08838834764831845f;  // 1/sqrt(128)
    {
        // score[i][j] = q[i] . k[j]
        const int i = tid >> 4, j = tid & 15;
        float acc = 0.f;
#pragma unroll 4
        for (int k4 = 0; k4 < 32; k4++) {
            const float4 a  = *reinterpret_cast<const float4*>(&sm.qq[i][k4 * 4]);
            const float4 bb = *reinterpret_cast<const float4*>(&sm.kk[j][k4 * 4]);
            acc = fmaf(a.x, bb.x, acc);
            acc = fmaf(a.y, bb.y, acc);
            acc = fmaf(a.z, bb.z, acc);
            acc = fmaf(a.w, bb.w, acc);
        }
        sm.w[i][j] = acc * scale;
    }
    for (int idx = tid; idx < NN * MM; idx += 256) {
        const int i = idx >> 5, m = idx & 31;
        float acc = 0.f;
#pragma unroll 4
        for (int k4 = 0; k4 < 32; k4++) {
            const float4 a  = *reinterpret_cast<const float4*>(&sm.qo[i][k4 * 4]);
            const float4 bb = *reinterpret_cast<const float4*>(&sm.ko[m][k4 * 4]);
            acc = fmaf(a.x, bb.x, acc);
            acc = fmaf(a.y, bb.y, acc);
            acc = fmaf(a.z, bb.z, acc);
            acc = fmaf(a.w, bb.w, acc);
        }
        sm.wo[i][m] = acc * scale;
    }
    __syncthreads();

    // ---------------- Softmaxes ----------------
    if (tid < 16) {
        // row softmax of sm.w (axis=-1)
        float mx = -CUDART_INF_F;
#pragma unroll
        for (int j = 0; j < 16; j++) mx = fmaxf(mx, sm.w[tid][j]);
        float s = 0.f;
#pragma unroll
        for (int j = 0; j < 16; j++) { float e = expf(sm.w[tid][j] - mx); sm.w[tid][j] = e; s += e; }
        const float inv = 1.f / s;
#pragma unroll
        for (int j = 0; j < 16; j++) sm.w[tid][j] *= inv;
    } else if (tid >= 32 && tid < 64) {
        // column softmax of sm.wo (axis=1 of [B,N,M])
        const int m = tid - 32;
        float mx = -CUDART_INF_F;
#pragma unroll
        for (int i = 0; i < 16; i++) mx = fmaxf(mx, sm.wo[i][m]);
        float s = 0.f;
#pragma unroll
        for (int i = 0; i < 16; i++) { float e = expf(sm.wo[i][m] - mx); sm.wo[i][m] = e; s += e; }
        const float inv = 1.f / s;
#pragma unroll
        for (int i = 0; i < 16; i++) sm.wo[i][m] *= inv;
    }
    __syncthreads();

    // Write attention outputs
    out_w[(size_t)b * 256 + tid] = (&sm.w[0][0])[tid];
    for (int idx = tid; idx < 512; idx += 256)
        out_wo[(size_t)b * 512 + idx] = (&sm.wo[0][0])[idx];

    // ---------------- Weighted aggregation ----------------
    gemm_rc<NN, 16, 128, 0, false>(&sm.w[0][0],  16, &sm.avact[0][0], nullptr, &sm.base_[0][0]);
    gemm_rc<NN, 32, 128, 0, false>(&sm.wo[0][0], 32, &sm.avo[0][0],   nullptr, &sm.wavo[0][0]);
    __syncthreads();

    // u = base @ W1[:128] + wav_o @ W1[128:] ; v = delta @ W1[:128]
    gemm_rc<NN, 128, 64, 0, false>(&sm.base_[0][0], 128, W1,            nullptr,     &sm.u[0][0]);
    gemm_rc<NN, 128, 64, 0, true >(&sm.wavo[0][0],  128, W1 + 128 * 64, &sm.u[0][0], &sm.u[0][0]);
    gemm_rc<NN, 128, 64, 0, false>(&sm.delta[0][0], 128, W1,            nullptr,     &sm.v[0][0]);
    __syncthreads();

    // ---------------- Final value ----------------
    {
        const int i = tid >> 4, j = tid & 15;
        const float wt = sm.w[i][j];
        float acc = 0.f;
#pragma unroll 8
        for (int d = 0; d < 64; d++) {
            float h = fmaf(wt, sm.v[j][d], sm.u[i][d]);
            h = (h > 0.f) ? h : 0.01f * h;
            acc = fmaf(h, sm.w2[d], acc);
        }
        out_value[(size_t)b * 256 + tid] = acc;
    }
}

extern "C" void kernel_launch(void* const* d_in, const int* in_sizes, int n_in,
                              void* d_out, int out_size) {
    const float* states    = (const float*)d_in[0];
    const float* policies  = (const float*)d_in[1];
    const float* actions   = (const float*)d_in[2];
    const float* states_o  = (const float*)d_in[3];
    const float* actions_o = (const float*)d_in[4];
    const float* Wk  = (const float*)d_in[5];
    const float* Wq  = (const float*)d_in[6];
    const float* Wv  = (const float*)d_in[7];
    const float* Wko = (const float*)d_in[8];
    const float* Wqo = (const float*)d_in[9];
    const float* Wvo = (const float*)d_in[10];
    const float* W1  = (const float*)d_in[11];
    const float* W2  = (const float*)d_in[12];

    float* out       = (float*)d_out;
    float* out_value = out;                         // [B,N,N,1]  -> 32768
    float* out_w     = out + BB * NN * NN;          // [B,N,N]    -> 32768
    float* out_wo    = out + 2 * BB * NN * NN;      // [B,N,M,1]  -> 65536

    cudaFuncSetAttribute(critic_kernel,
                         cudaFuncAttributeMaxDynamicSharedMemorySize,
                         (int)sizeof(Smem));

    critic_kernel<<<BB, 256, sizeof(Smem)>>>(states, policies, actions,
                                             states_o, actions_o,
                                             Wk, Wq, Wv, Wko, Wqo, Wvo, W1, W2,
                                             out_value, out_w, out_wo);
}

// round 2
// speedup vs baseline: 1.4689x; 1.4689x over previous
#include <cuda_runtime.h>

#define BB 128
typedef unsigned long long u64;

__device__ __forceinline__ u64 pack2(float x, float y){
    u64 r; asm("mov.b64 %0,{%1,%2};" : "=l"(r) : "f"(x), "f"(y)); return r;
}
__device__ __forceinline__ void unpack2(u64 a, float& x, float& y){
    asm("mov.b64 {%0,%1},%2;" : "=f"(x), "=f"(y) : "l"(a));
}
__device__ __forceinline__ u64 fma2(u64 a, u64 b, u64 c){
    u64 d; asm("fma.rn.f32x2 %0,%1,%2,%3;" : "=l"(d) : "l"(a), "l"(b), "l"(c)); return d;
}
__device__ __forceinline__ float fast_tanh(float x){
    float e = __expf(2.0f * x);
    return 1.0f - __fdividef(2.0f, e + 1.0f);
}

// Padded strides (floats) to keep 16B alignment + avoid bank conflicts
#define ST_T16 20   // [K][16] transposed tiles
#define ST_T32 36   // [K][32] transposed tiles
#define ST_RM  132  // row-major [R][128] tiles
#define ST_UV  68   // row-major [16][64] tiles

struct Smem {
    float sT  [128 * ST_T16];  // states^T
    float oaoT[136 * ST_T32];  // [states_o|actions_o]^T
    float act [16 * 8];
    float pol [16 * 8];
    float kkT [128 * ST_T16];
    float qqT [128 * ST_T16];
    float qoT [128 * ST_T16];
    float t   [16 * ST_RM];    // states @ Wv[:128], row-major
    float koT [128 * ST_T32];
    float avo [32 * ST_RM];    // row-major (used as B operand later)
    float avact[16 * ST_RM];   // row-major
    float deltaT[128 * ST_T16];
    float w  [256];
    float wT [256];
    float wo [512];
    float woT[512];
    float baseT [128 * ST_T16];
    float wavoT [128 * ST_T16];
    float u  [16 * ST_UV];
    float v  [16 * ST_UV];
    float w2 [64];
};

__global__ __launch_bounds__(512, 1)
void critic_kernel(const float* __restrict__ states,
                   const float* __restrict__ policies,
                   const float* __restrict__ actions,
                   const float* __restrict__ states_o,
                   const float* __restrict__ actions_o,
                   const float* __restrict__ Wk,  const float* __restrict__ Wq,
                   const float* __restrict__ Wv,  const float* __restrict__ Wko,
                   const float* __restrict__ Wqo, const float* __restrict__ Wvo,
                   const float* __restrict__ W1,  const float* __restrict__ W2,
                   float* __restrict__ out_value,
                   float* __restrict__ out_w,
                   float* __restrict__ out_wo)
{
    extern __shared__ unsigned char smem_raw[];
    Smem& sm = *reinterpret_cast<Smem*>(smem_raw);

    const int b   = blockIdx.x;
    const int tid = threadIdx.x;

    // ============ Stage 0: load + transpose inputs ============
    {
        const int k  = tid & 127;
        const int g  = tid >> 7;       // 0..3
        const int r0 = g * 4;
        // states^T : sT[k][r], coalesced global reads along k
        const float* S = states + (size_t)b * 16 * 128;
        {
            float a0 = S[(r0 + 0) * 128 + k];
            float a1 = S[(r0 + 1) * 128 + k];
            float a2 = S[(r0 + 2) * 128 + k];
            float a3 = S[(r0 + 3) * 128 + k];
            *reinterpret_cast<float4*>(&sm.sT[k * ST_T16 + r0]) = make_float4(a0, a1, a2, a3);
        }
        // states_o^T (rows 0..127 of oaoT), 32 agent rows
        const float* SO = states_o + (size_t)b * 32 * 128;
#pragma unroll
        for (int h = 0; h < 32; h += 16) {
            float a0 = SO[(r0 + h + 0) * 128 + k];
            float a1 = SO[(r0 + h + 1) * 128 + k];
            float a2 = SO[(r0 + h + 2) * 128 + k];
            float a3 = SO[(r0 + h + 3) * 128 + k];
            *reinterpret_cast<float4*>(&sm.oaoT[k * ST_T32 + r0 + h]) = make_float4(a0, a1, a2, a3);
        }
        // actions_o^T (rows 128..135 of oaoT)
        if (tid < 256) {
            int kk8 = tid >> 5, m = tid & 31;
            sm.oaoT[(128 + kk8) * ST_T32 + m] = actions_o[(size_t)b * 32 * 8 + m * 8 + kk8];
        }
        // actions / policies (row-major, tiny)
        if (tid < 128) {
            int r = tid >> 3, c = tid & 7;
            sm.act[r * 8 + c] = actions[(size_t)b * 16 * 8 + r * 8 + c];
            sm.pol[r * 8 + c] = policies[(size_t)b * 16 * 8 + r * 8 + c];
        }
        if (tid < 64) sm.w2[tid] = W2[tid];
    }
    __syncthreads();

    // ============ Stage 1a: fused projections (Wk|Wq|Wqo|Wv[:128]) ============
    // C_total = 512, one column per thread, RB = 16 rows, packed f32x2
    {
        const int c   = tid;
        const int mat = c >> 7;
        const int col = c & 127;
        const float* Wm = (mat == 0 ? Wk : mat == 1 ? Wq : mat == 2 ? Wqo : Wv) + col;

        u64 acc[8];
#pragma unroll
        for (int p = 0; p < 8; p++) acc[p] = 0ull;

#pragma unroll 4
        for (int k = 0; k < 128; k++) {
            float wv = Wm[k * 128];
            u64 wp = pack2(wv, wv);
            const ulonglong2* A = reinterpret_cast<const ulonglong2*>(&sm.sT[k * ST_T16]);
            ulonglong2 a0 = A[0], a1 = A[1], a2 = A[2], a3 = A[3];
            acc[0] = fma2(a0.x, wp, acc[0]);
            acc[1] = fma2(a0.y, wp, acc[1]);
            acc[2] = fma2(a1.x, wp, acc[2]);
            acc[3] = fma2(a1.y, wp, acc[3]);
            acc[4] = fma2(a2.x, wp, acc[4]);
            acc[5] = fma2(a2.y, wp, acc[5]);
            acc[6] = fma2(a3.x, wp, acc[6]);
            acc[7] = fma2(a3.y, wp, acc[7]);
        }
        if (mat < 3) {
            float* oT = (mat == 0 ? sm.kkT : mat == 1 ? sm.qqT : sm.qoT) + col * ST_T16;
            ulonglong2 s0 = {acc[0], acc[1]}, s1 = {acc[2], acc[3]};
            ulonglong2 s2 = {acc[4], acc[5]}, s3 = {acc[6], acc[7]};
            *reinterpret_cast<ulonglong2*>(oT + 0)  = s0;
            *reinterpret_cast<ulonglong2*>(oT + 4)  = s1;
            *reinterpret_cast<ulonglong2*>(oT + 8)  = s2;
            *reinterpret_cast<ulonglong2*>(oT + 12) = s3;
        } else {
#pragma unroll
            for (int p = 0; p < 8; p++) {
                float x, y; unpack2(acc[p], x, y);
                sm.t[(2 * p + 0) * ST_RM + col] = x;
                sm.t[(2 * p + 1) * ST_RM + col] = y;
            }
        }
    }

    // ============ Stage 1b: fused other-agent GEMM (Wko | Wvo) ============
    // C_total = 256, G = 2 row-groups of 16 (R = 32)
    {
        const int g   = tid >> 8;       // 0..1
        const int c   = tid & 255;
        const int r0  = g * 16;
        const bool isK = (c < 128);
        const int col = c & 127;
        const float* Wm = (isK ? Wko : Wvo) + col;

        u64 acc[8];
#pragma unroll
        for (int p = 0; p < 8; p++) acc[p] = 0ull;

#pragma unroll 4
        for (int k = 0; k < 128; k++) {
            float wv = Wm[k * 128];
            u64 wp = pack2(wv, wv);
            const ulonglong2* A = reinterpret_cast<const ulonglong2*>(&sm.oaoT[k * ST_T32 + r0]);
            ulonglong2 a0 = A[0], a1 = A[1], a2 = A[2], a3 = A[3];
            acc[0] = fma2(a0.x, wp, acc[0]);
            acc[1] = fma2(a0.y, wp, acc[1]);
            acc[2] = fma2(a1.x, wp, acc[2]);
            acc[3] = fma2(a1.y, wp, acc[3]);
            acc[4] = fma2(a2.x, wp, acc[4]);
            acc[5] = fma2(a2.y, wp, acc[5]);
            acc[6] = fma2(a3.x, wp, acc[6]);
            acc[7] = fma2(a3.y, wp, acc[7]);
        }
        if (isK) {
            float* oT = sm.koT + col * ST_T32 + r0;
            ulonglong2 s0 = {acc[0], acc[1]}, s1 = {acc[2], acc[3]};
            ulonglong2 s2 = {acc[4], acc[5]}, s3 = {acc[6], acc[7]};
            *reinterpret_cast<ulonglong2*>(oT + 0)  = s0;
            *reinterpret_cast<ulonglong2*>(oT + 4)  = s1;
            *reinterpret_cast<ulonglong2*>(oT + 8)  = s2;
            *reinterpret_cast<ulonglong2*>(oT + 12) = s3;
        } else {
            // tail K 128..135 (actions_other part of Wvo), then tanh
#pragma unroll
            for (int k = 128; k < 136; k++) {
                float wv = Wm[k * 128];
                u64 wp = pack2(wv, wv);
                const ulonglong2* A = reinterpret_cast<const ulonglong2*>(&sm.oaoT[k * ST_T32 + r0]);
                ulonglong2 a0 = A[0], a1 = A[1], a2 = A[2], a3 = A[3];
                acc[0] = fma2(a0.x, wp, acc[0]);
                acc[1] = fma2(a0.y, wp, acc[1]);
                acc[2] = fma2(a1.x, wp, acc[2]);
                acc[3] = fma2(a1.y, wp, acc[3]);
                acc[4] = fma2(a2.x, wp, acc[4]);
                acc[5] = fma2(a2.y, wp, acc[5]);
                acc[6] = fma2(a3.x, wp, acc[6]);
                acc[7] = fma2(a3.y, wp, acc[7]);
            }
#pragma unroll
            for (int p = 0; p < 8; p++) {
                float x, y; unpack2(acc[p], x, y);
                sm.avo[(r0 + 2 * p + 0) * ST_RM + col] = fast_tanh(x);
                sm.avo[(r0 + 2 * p + 1) * ST_RM + col] = fast_tanh(y);
            }
        }
    }
    __syncthreads();

    // ============ Stage 2: avact / deltaT (K=8 tails) + attention scores ============
    {
        const int g  = tid >> 7;    // 0..3
        const int c  = tid & 127;
        const int r0 = g * 4;
        float aa[4], ap[4];
#pragma unroll
        for (int i = 0; i < 4; i++) {
            float tv = sm.t[(r0 + i) * ST_RM + c];
            aa[i] = tv; ap[i] = tv;
        }
#pragma unroll
        for (int k = 0; k < 8; k++) {
            float wv = Wv[(128 + k) * 128 + c];
#pragma unroll
            for (int i = 0; i < 4; i++) {
                aa[i] = fmaf(sm.act[(r0 + i) * 8 + k], wv, aa[i]);
                ap[i] = fmaf(sm.pol[(r0 + i) * 8 + k], wv, ap[i]);
            }
        }
        float dl[4];
#pragma unroll
        for (int i = 0; i < 4; i++) {
            float ta = fast_tanh(aa[i]);
            float tp = fast_tanh(ap[i]);
            sm.avact[(r0 + i) * ST_RM + c] = ta;
            dl[i] = tp - ta;
        }
        *reinterpret_cast<float4*>(&sm.deltaT[c * ST_T16 + r0]) = make_float4(dl[0], dl[1], dl[2], dl[3]);
    }
    const float scale = 0.08838834764831845f;  // 1/sqrt(128)
    {
        // wo scores: all 512 threads, one (i,m) each
        const int i = tid >> 5, m = tid & 31;
        float acc = 0.f;
#pragma unroll 8
        for (int k = 0; k < 128; k++)
            acc = fmaf(sm.qoT[k * ST_T16 + i], sm.koT[k * ST_T32 + m], acc);
        sm.wo[i * 32 + m] = acc * scale;
    }
    if (tid < 256) {
        const int i = tid >> 4, j = tid & 15;
        float acc = 0.f;
#pragma unroll 8
        for (int k = 0; k < 128; k++)
            acc = fmaf(sm.qqT[k * ST_T16 + i], sm.kkT[k * ST_T16 + j], acc);
        sm.w[i * 16 + j] = acc * scale;
    }
    __syncthreads();

    // ============ Stage 3: softmaxes (+ transposed copies + global writes) ============
    if (tid < 16) {
        const int i = tid;
        float mx = -1e30f;
#pragma unroll
        for (int j = 0; j < 16; j++) mx = fmaxf(mx, sm.w[i * 16 + j]);
        float s = 0.f, e[16];
#pragma unroll
        for (int j = 0; j < 16; j++) { e[j] = __expf(sm.w[i * 16 + j] - mx); s += e[j]; }
        const float inv = __fdividef(1.f, s);
#pragma unroll
        for (int j = 0; j < 16; j++) {
            float p = e[j] * inv;
            sm.w[i * 16 + j]  = p;
            sm.wT[j * 16 + i] = p;
            out_w[(size_t)b * 256 + i * 16 + j] = p;
        }
    } else if (tid < 48) {
        const int m = tid - 16;
        float mx = -1e30f;
#pragma unroll
        for (int i = 0; i < 16; i++) mx = fmaxf(mx, sm.wo[i * 32 + m]);
        float s = 0.f, e[16];
#pragma unroll
        for (int i = 0; i < 16; i++) { e[i] = __expf(sm.wo[i * 32 + m] - mx); s += e[i]; }
        const float inv = __fdividef(1.f, s);
#pragma unroll
        for (int i = 0; i < 16; i++) {
            float p = e[i] * inv;
            sm.wo[i * 32 + m]  = p;
            sm.woT[m * 16 + i] = p;
            out_wo[(size_t)b * 512 + i * 32 + m] = p;
        }
    }
    __syncthreads();

    // ============ Stage 4: aggregation GEMMs -> baseT, wavoT ============
    {
        const int g  = tid >> 7;
        const int c  = tid & 127;
        const int r0 = g * 4;
        // base[i][c] = sum_j w[i][j] * avact[j][c]
        u64 a0 = 0ull, a1 = 0ull;
#pragma unroll
        for (int k = 0; k < 16; k++) {
            float wv = sm.avact[k * ST_RM + c];
            u64 wp = pack2(wv, wv);
            ulonglong2 a = *reinterpret_cast<const ulonglong2*>(&sm.wT[k * 16 + r0]);
            a0 = fma2(a.x, wp, a0);
            a1 = fma2(a.y, wp, a1);
        }
        ulonglong2 s0 = {a0, a1};
        *reinterpret_cast<ulonglong2*>(&sm.baseT[c * ST_T16 + r0]) = s0;

        // wavo[i][c] = sum_m wo[i][m] * avo[m][c]
        a0 = 0ull; a1 = 0ull;
#pragma unroll
        for (int k = 0; k < 32; k++) {
            float wv = sm.avo[k * ST_RM + c];
            u64 wp = pack2(wv, wv);
            ulonglong2 a = *reinterpret_cast<const ulonglong2*>(&sm.woT[k * 16 + r0]);
            a0 = fma2(a.x, wp, a0);
            a1 = fma2(a.y, wp, a1);
        }
        ulonglong2 s1 = {a0, a1};
        *reinterpret_cast<ulonglong2*>(&sm.wavoT[c * ST_T16 + r0]) = s1;
    }
    __syncthreads();

    // ============ Stage 5: u / v hidden-layer GEMMs ============
    {
        const int g   = tid >> 7;
        const int cc  = tid & 127;
        const int r0  = g * 4;
        const bool isU = (cc < 64);
        const int col = cc & 63;
        const float* A1 = isU ? sm.baseT : sm.deltaT;

        u64 a0 = 0ull, a1 = 0ull;
#pragma unroll 4
        for (int k = 0; k < 128; k++) {
            float wv = W1[k * 64 + col];
            u64 wp = pack2(wv, wv);
            ulonglong2 a = *reinterpret_cast<const ulonglong2*>(&A1[k * ST_T16 + r0]);
            a0 = fma2(a.x, wp, a0);
            a1 = fma2(a.y, wp, a1);
        }
        if (isU) {
#pragma unroll 4
            for (int k = 0; k < 128; k++) {
                float wv = W1[(128 + k) * 64 + col];
                u64 wp = pack2(wv, wv);
                ulonglong2 a = *reinterpret_cast<const ulonglong2*>(&sm.wavoT[k * ST_T16 + r0]);
                a0 = fma2(a.x, wp, a0);
                a1 = fma2(a.y, wp, a1);
            }
        }
        float* o = (isU ? sm.u : sm.v);
        float x0, x1, x2, x3;
        unpack2(a0, x0, x1);
        unpack2(a1, x2, x3);
        o[(r0 + 0) * ST_UV + col] = x0;
        o[(r0 + 1) * ST_UV + col] = x1;
        o[(r0 + 2) * ST_UV + col] = x2;
        o[(r0 + 3) * ST_UV + col] = x3;
    }
    __syncthreads();

    // ============ Stage 6: final value ============
    {
        const int p = tid >> 1, h = tid & 1;
        const int i = p >> 4, j = p & 15;
        const float wt = sm.w[i * 16 + j];
        float acc = 0.f;
        const int d0 = h * 32;
#pragma unroll 8
        for (int d = d0; d < d0 + 32; d++) {
            float hh = fmaf(wt, sm.v[j * ST_UV + d], sm.u[i * ST_UV + d]);
            hh = (hh > 0.f) ? hh : 0.01f * hh;
            acc = fmaf(hh, sm.w2[d], acc);
        }
        acc += __shfl_xor_sync(0xffffffffu, acc, 1);
        if (h == 0) out_value[(size_t)b * 256 + p] = acc;
    }
}

extern "C" void kernel_launch(void* const* d_in, const int* in_sizes, int n_in,
                              void* d_out, int out_size) {
    const float* states    = (const float*)d_in[0];
    const float* policies  = (const float*)d_in[1];
    const float* actions   = (const float*)d_in[2];
    const float* states_o  = (const float*)d_in[3];
    const float* actions_o = (const float*)d_in[4];
    const float* Wk  = (const float*)d_in[5];
    const float* Wq  = (const float*)d_in[6];
    const float* Wv  = (const float*)d_in[7];
    const float* Wko = (const float*)d_in[8];
    const float* Wqo = (const float*)d_in[9];
    const float* Wvo = (const float*)d_in[10];
    const float* W1  = (const float*)d_in[11];
    const float* W2  = (const float*)d_in[12];

    float* out       = (float*)d_out;
    float* out_value = out;                    // [B,N,N,1]
    float* out_w     = out + BB * 256;         // [B,N,N]
    float* out_wo    = out + 2 * BB * 256;     // [B,N,M,1]

    cudaFuncSetAttribute(critic_kernel,
                         cudaFuncAttributeMaxDynamicSharedMemorySize,
                         (int)sizeof(Smem));

    critic_kernel<<<BB, 512, sizeof(Smem)>>>(states, policies, actions,
                                             states_o, actions_o,
                                             Wk, Wq, Wv, Wko, Wqo, Wvo, W1, W2,
                                             out_value, out_w, out_wo);
}

// round 3
// speedup vs baseline: 2.0427x; 1.3906x over previous
#include <cuda_runtime.h>

#define BB 128
typedef unsigned long long u64;

__device__ __forceinline__ u64 pack2(float x, float y){
    u64 r; asm("mov.b64 %0,{%1,%2};" : "=l"(r) : "f"(x), "f"(y)); return r;
}
__device__ __forceinline__ void unpack2(u64 a, float& x, float& y){
    asm("mov.b64 {%0,%1},%2;" : "=f"(x), "=f"(y) : "l"(a));
}
__device__ __forceinline__ u64 fma2(u64 a, u64 b, u64 c){
    u64 d; asm("fma.rn.f32x2 %0,%1,%2,%3;" : "=l"(d) : "l"(a), "l"(b), "l"(c)); return d;
}
__device__ __forceinline__ float fast_tanh(float x){
    float e = __expf(2.0f * x);
    return 1.0f - __fdividef(2.0f, e + 1.0f);
}

#define ST_T16 20   // [K][16] transposed tiles (floats)
#define ST_T32 36   // [K][32] transposed tiles
#define ST_RM  132  // row-major [16][128] tile
#define ST_PX  66   // row-major [R][64] tiles (P, X, u, v)

struct Smem {
    float sT    [128 * ST_T16];  // states^T
    float oaoT  [136 * ST_T32];  // [states_o | actions_o]^T
    float act   [16 * 8];
    float pol   [16 * 8];
    float kkT   [128 * ST_T16];
    float qqT   [128 * ST_T16];
    float qoT   [128 * ST_T16];
    float t     [16 * ST_RM];    // states @ Wv[:128], row-major
    float koT   [128 * ST_T32];
    float avoT  [128 * ST_T32];  // tanh(oao @ Wvo), transposed
    float avactT[128 * ST_T16];
    float deltaT[128 * ST_T16];
    float w     [256];
    float wo    [512];
    float P     [16 * ST_PX];    // avact @ W1a
    float X     [32 * ST_PX];    // avo   @ W1b
    float u     [16 * ST_PX];
    float v     [16 * ST_PX];    // delta @ W1a
    float w2    [64];
};

__global__ __launch_bounds__(512, 1)
void critic_kernel(const float* __restrict__ states,
                   const float* __restrict__ policies,
                   const float* __restrict__ actions,
                   const float* __restrict__ states_o,
                   const float* __restrict__ actions_o,
                   const float* __restrict__ Wk,  const float* __restrict__ Wq,
                   const float* __restrict__ Wv,  const float* __restrict__ Wko,
                   const float* __restrict__ Wqo, const float* __restrict__ Wvo,
                   const float* __restrict__ W1,  const float* __restrict__ W2,
                   float* __restrict__ out_value,
                   float* __restrict__ out_w,
                   float* __restrict__ out_wo)
{
    extern __shared__ unsigned char smem_raw[];
    Smem& sm = *reinterpret_cast<Smem*>(smem_raw);

    const int b   = blockIdx.x;
    const int tid = threadIdx.x;

    // ============ Stage 0: load + transpose inputs ============
    {
        const int k  = tid & 127;
        const int g  = tid >> 7;       // 0..3
        const int r0 = g * 4;
        const float* S = states + (size_t)b * 16 * 128;
        {
            float a0 = S[(r0 + 0) * 128 + k];
            float a1 = S[(r0 + 1) * 128 + k];
            float a2 = S[(r0 + 2) * 128 + k];
            float a3 = S[(r0 + 3) * 128 + k];
            *reinterpret_cast<float4*>(&sm.sT[k * ST_T16 + r0]) = make_float4(a0, a1, a2, a3);
        }
        const float* SO = states_o + (size_t)b * 32 * 128;
#pragma unroll
        for (int h = 0; h < 32; h += 16) {
            float a0 = SO[(r0 + h + 0) * 128 + k];
            float a1 = SO[(r0 + h + 1) * 128 + k];
            float a2 = SO[(r0 + h + 2) * 128 + k];
            float a3 = SO[(r0 + h + 3) * 128 + k];
            *reinterpret_cast<float4*>(&sm.oaoT[k * ST_T32 + r0 + h]) = make_float4(a0, a1, a2, a3);
        }
        if (tid < 256) {
            int kk8 = tid >> 5, m = tid & 31;
            sm.oaoT[(128 + kk8) * ST_T32 + m] = actions_o[(size_t)b * 32 * 8 + m * 8 + kk8];
        }
        if (tid < 128) {
            int r = tid >> 3, c = tid & 7;
            sm.act[r * 8 + c] = actions[(size_t)b * 16 * 8 + r * 8 + c];
            sm.pol[r * 8 + c] = policies[(size_t)b * 16 * 8 + r * 8 + c];
        }
        if (tid < 64) sm.w2[tid] = W2[tid];
    }
    __syncthreads();

    // ============ Stage 1: warp-specialized projection GEMMs ============
    if (tid < 256) {
        // warps 0-7: states projections (Wk | Wq | Wqo | Wv[:128]); 512 cols x 16 rows
        const int lane = tid & 31;
        const int warp = tid >> 5;       // 0..7
        const int mat  = warp & 3;
        const int r0   = (warp >> 2) * 8; // 0 or 8
        const int col  = lane * 4;
        const float* Wm = (mat == 0 ? Wk : mat == 1 ? Wq : mat == 2 ? Wqo : Wv) + col;

        u64 acc[4][4];
#pragma unroll
        for (int j = 0; j < 4; j++)
#pragma unroll
            for (int p = 0; p < 4; p++) acc[j][p] = 0ull;

#pragma unroll 4
        for (int k = 0; k < 128; k++) {
            const float4 w4 = *reinterpret_cast<const float4*>(Wm + k * 128);
            const ulonglong2 A0 = *reinterpret_cast<const ulonglong2*>(&sm.sT[k * ST_T16 + r0]);
            const ulonglong2 A1 = *reinterpret_cast<const ulonglong2*>(&sm.sT[k * ST_T16 + r0 + 4]);
            const u64 wp0 = pack2(w4.x, w4.x);
            const u64 wp1 = pack2(w4.y, w4.y);
            const u64 wp2 = pack2(w4.z, w4.z);
            const u64 wp3 = pack2(w4.w, w4.w);
            acc[0][0] = fma2(A0.x, wp0, acc[0][0]);
            acc[0][1] = fma2(A0.y, wp0, acc[0][1]);
            acc[0][2] = fma2(A1.x, wp0, acc[0][2]);
            acc[0][3] = fma2(A1.y, wp0, acc[0][3]);
            acc[1][0] = fma2(A0.x, wp1, acc[1][0]);
            acc[1][1] = fma2(A0.y, wp1, acc[1][1]);
            acc[1][2] = fma2(A1.x, wp1, acc[1][2]);
            acc[1][3] = fma2(A1.y, wp1, acc[1][3]);
            acc[2][0] = fma2(A0.x, wp2, acc[2][0]);
            acc[2][1] = fma2(A0.y, wp2, acc[2][1]);
            acc[2][2] = fma2(A1.x, wp2, acc[2][2]);
            acc[2][3] = fma2(A1.y, wp2, acc[2][3]);
            acc[3][0] = fma2(A0.x, wp3, acc[3][0]);
            acc[3][1] = fma2(A0.y, wp3, acc[3][1]);
            acc[3][2] = fma2(A1.x, wp3, acc[3][2]);
            acc[3][3] = fma2(A1.y, wp3, acc[3][3]);
        }
        if (mat < 3) {
            float* oT = (mat == 0 ? sm.kkT : mat == 1 ? sm.qqT : sm.qoT);
#pragma unroll
            for (int j = 0; j < 4; j++) {
                float* d = oT + (col + j) * ST_T16 + r0;
                ulonglong2 s0 = {acc[j][0], acc[j][1]};
                ulonglong2 s1 = {acc[j][2], acc[j][3]};
                *reinterpret_cast<ulonglong2*>(d)     = s0;
                *reinterpret_cast<ulonglong2*>(d + 4) = s1;
            }
        } else {
            // t row-major [16][ST_RM]
#pragma unroll
            for (int p = 0; p < 4; p++) {
                float x0, y0, x1, y1, x2, y2, x3, y3;
                unpack2(acc[0][p], x0, y0);
                unpack2(acc[1][p], x1, y1);
                unpack2(acc[2][p], x2, y2);
                unpack2(acc[3][p], x3, y3);
                *reinterpret_cast<float4*>(&sm.t[(r0 + 2 * p + 0) * ST_RM + col]) = make_float4(x0, x1, x2, x3);
                *reinterpret_cast<float4*>(&sm.t[(r0 + 2 * p + 1) * ST_RM + col]) = make_float4(y0, y1, y2, y3);
            }
        }
    } else {
        // warps 8-15: other-agent projections (Wko | Wvo); 256 cols x 32 rows
        const int tid2 = tid - 256;
        const int lane = tid2 & 31;
        const int wrp  = tid2 >> 5;      // 0..7
        const int mat  = wrp & 1;        // 0 = Wko, 1 = Wvo
        const int r0   = (wrp >> 1) * 8; // 0,8,16,24
        const int col  = lane * 4;
        const float* Wm = (mat ? Wvo : Wko) + col;

        u64 acc[4][4];
#pragma unroll
        for (int j = 0; j < 4; j++)
#pragma unroll
            for (int p = 0; p < 4; p++) acc[j][p] = 0ull;

#pragma unroll 4
        for (int k = 0; k < 128; k++) {
            const float4 w4 = *reinterpret_cast<const float4*>(Wm + k * 128);
            const ulonglong2 A0 = *reinterpret_cast<const ulonglong2*>(&sm.oaoT[k * ST_T32 + r0]);
            const ulonglong2 A1 = *reinterpret_cast<const ulonglong2*>(&sm.oaoT[k * ST_T32 + r0 + 4]);
            const u64 wp0 = pack2(w4.x, w4.x);
            const u64 wp1 = pack2(w4.y, w4.y);
            const u64 wp2 = pack2(w4.z, w4.z);
            const u64 wp3 = pack2(w4.w, w4.w);
            acc[0][0] = fma2(A0.x, wp0, acc[0][0]);
            acc[0][1] = fma2(A0.y, wp0, acc[0][1]);
            acc[0][2] = fma2(A1.x, wp0, acc[0][2]);
            acc[0][3] = fma2(A1.y, wp0, acc[0][3]);
            acc[1][0] = fma2(A0.x, wp1, acc[1][0]);
            acc[1][1] = fma2(A0.y, wp1, acc[1][1]);
            acc[1][2] = fma2(A1.x, wp1, acc[1][2]);
            acc[1][3] = fma2(A1.y, wp1, acc[1][3]);
            acc[2][0] = fma2(A0.x, wp2, acc[2][0]);
            acc[2][1] = fma2(A0.y, wp2, acc[2][1]);
            acc[2][2] = fma2(A1.x, wp2, acc[2][2]);
            acc[2][3] = fma2(A1.y, wp2, acc[2][3]);
            acc[3][0] = fma2(A0.x, wp3, acc[3][0]);
            acc[3][1] = fma2(A0.y, wp3, acc[3][1]);
            acc[3][2] = fma2(A1.x, wp3, acc[3][2]);
            acc[3][3] = fma2(A1.y, wp3, acc[3][3]);
        }
        if (mat == 0) {
#pragma unroll
            for (int j = 0; j < 4; j++) {
                float* d = sm.koT + (col + j) * ST_T32 + r0;
                ulonglong2 s0 = {acc[j][0], acc[j][1]};
                ulonglong2 s1 = {acc[j][2], acc[j][3]};
                *reinterpret_cast<ulonglong2*>(d)     = s0;
                *reinterpret_cast<ulonglong2*>(d + 4) = s1;
            }
        } else {
            // Wvo tail: K 128..135 (actions_other)
#pragma unroll
            for (int k = 128; k < 136; k++) {
                const float4 w4 = *reinterpret_cast<const float4*>(Wm + k * 128);
                const ulonglong2 A0 = *reinterpret_cast<const ulonglong2*>(&sm.oaoT[k * ST_T32 + r0]);
                const ulonglong2 A1 = *reinterpret_cast<const ulonglong2*>(&sm.oaoT[k * ST_T32 + r0 + 4]);
                const u64 wp0 = pack2(w4.x, w4.x);
                const u64 wp1 = pack2(w4.y, w4.y);
                const u64 wp2 = pack2(w4.z, w4.z);
                const u64 wp3 = pack2(w4.w, w4.w);
                acc[0][0] = fma2(A0.x, wp0, acc[0][0]);
                acc[0][1] = fma2(A0.y, wp0, acc[0][1]);
                acc[0][2] = fma2(A1.x, wp0, acc[0][2]);
                acc[0][3] = fma2(A1.y, wp0, acc[0][3]);
                acc[1][0] = fma2(A0.x, wp1, acc[1][0]);
                acc[1][1] = fma2(A0.y, wp1, acc[1][1]);
                acc[1][2] = fma2(A1.x, wp1, acc[1][2]);
                acc[1][3] = fma2(A1.y, wp1, acc[1][3]);
                acc[2][0] = fma2(A0.x, wp2, acc[2][0]);
                acc[2][1] = fma2(A0.y, wp2, acc[2][1]);
                acc[2][2] = fma2(A1.x, wp2, acc[2][2]);
                acc[2][3] = fma2(A1.y, wp2, acc[2][3]);
                acc[3][0] = fma2(A0.x, wp3, acc[3][0]);
                acc[3][1] = fma2(A0.y, wp3, acc[3][1]);
                acc[3][2] = fma2(A1.x, wp3, acc[3][2]);
                acc[3][3] = fma2(A1.y, wp3, acc[3][3]);
            }
#pragma unroll
            for (int j = 0; j < 4; j++) {
                float t0, t1, t2, t3, t4, t5, t6, t7;
                unpack2(acc[j][0], t0, t1);
                unpack2(acc[j][1], t2, t3);
                unpack2(acc[j][2], t4, t5);
                unpack2(acc[j][3], t6, t7);
                float* d = sm.avoT + (col + j) * ST_T32 + r0;
                *reinterpret_cast<float4*>(d)     = make_float4(fast_tanh(t0), fast_tanh(t1), fast_tanh(t2), fast_tanh(t3));
                *reinterpret_cast<float4*>(d + 4) = make_float4(fast_tanh(t4), fast_tanh(t5), fast_tanh(t6), fast_tanh(t7));
            }
        }
    }
    __syncthreads();

    // ============ Stage 2: avactT/deltaT tails + attention scores ============
    {
        const int g  = tid >> 7;    // 0..3
        const int c  = tid & 127;
        const int r0 = g * 4;
        float aa[4], ap[4];
#pragma unroll
        for (int i = 0; i < 4; i++) {
            float tv = sm.t[(r0 + i) * ST_RM + c];
            aa[i] = tv; ap[i] = tv;
        }
#pragma unroll
        for (int k = 0; k < 8; k++) {
            float wv = Wv[(128 + k) * 128 + c];
#pragma unroll
            for (int i = 0; i < 4; i++) {
                aa[i] = fmaf(sm.act[(r0 + i) * 8 + k], wv, aa[i]);
                ap[i] = fmaf(sm.pol[(r0 + i) * 8 + k], wv, ap[i]);
            }
        }
        float ta[4], dl[4];
#pragma unroll
        for (int i = 0; i < 4; i++) {
            ta[i] = fast_tanh(aa[i]);
            dl[i] = fast_tanh(ap[i]) - ta[i];
        }
        *reinterpret_cast<float4*>(&sm.avactT[c * ST_T16 + r0]) = make_float4(ta[0], ta[1], ta[2], ta[3]);
        *reinterpret_cast<float4*>(&sm.deltaT[c * ST_T16 + r0]) = make_float4(dl[0], dl[1], dl[2], dl[3]);
    }
    const float scale = 0.08838834764831845f;  // 1/sqrt(128)
    {
        const int i = tid >> 5, m = tid & 31;
        float acc = 0.f;
#pragma unroll 8
        for (int k = 0; k < 128; k++)
            acc = fmaf(sm.qoT[k * ST_T16 + i], sm.koT[k * ST_T32 + m], acc);
        sm.wo[i * 32 + m] = acc * scale;
    }
    if (tid < 256) {
        const int i = tid >> 4, j = tid & 15;
        float acc = 0.f;
#pragma unroll 8
        for (int k = 0; k < 128; k++)
            acc = fmaf(sm.qqT[k * ST_T16 + i], sm.kkT[k * ST_T16 + j], acc);
        sm.w[i * 16 + j] = acc * scale;
    }
    __syncthreads();

    // ============ Stage 3: softmaxes (few threads) + P/v/X GEMMs (all) ============
    if (tid < 16) {
        const int i = tid;
        float mx = -1e30f;
#pragma unroll
        for (int j = 0; j < 16; j++) mx = fmaxf(mx, sm.w[i * 16 + j]);
        float s = 0.f, e[16];
#pragma unroll
        for (int j = 0; j < 16; j++) { e[j] = __expf(sm.w[i * 16 + j] - mx); s += e[j]; }
        const float inv = __fdividef(1.f, s);
#pragma unroll
        for (int j = 0; j < 16; j++) {
            float p = e[j] * inv;
            sm.w[i * 16 + j] = p;
            out_w[(size_t)b * 256 + i * 16 + j] = p;
        }
    } else if (tid < 48) {
        const int m = tid - 16;
        float mx = -1e30f;
#pragma unroll
        for (int i = 0; i < 16; i++) mx = fmaxf(mx, sm.wo[i * 32 + m]);
        float s = 0.f, e[16];
#pragma unroll
        for (int i = 0; i < 16; i++) { e[i] = __expf(sm.wo[i * 32 + m] - mx); s += e[i]; }
        const float inv = __fdividef(1.f, s);
#pragma unroll
        for (int i = 0; i < 16; i++) {
            float p = e[i] * inv;
            sm.wo[i * 32 + m] = p;
            out_wo[(size_t)b * 512 + i * 32 + m] = p;
        }
    }
    // P = avact @ W1a, v = delta @ W1a, X = avo @ W1b (independent of softmax)
    {
        u64 a00 = 0ull, a01 = 0ull, a10 = 0ull, a11 = 0ull;
        const float* AT;
        const float* Wg;
        float* dst;
        int r0, strideA, col;
        if (tid < 256) {
            const int cq2 = tid & 31;
            const int rg  = tid >> 5;         // 0..7
            col = cq2 * 2;
            AT  = (rg < 4 ? sm.avactT : sm.deltaT);
            r0  = (rg & 3) * 4;
            strideA = ST_T16;
            Wg  = W1;
            dst = (rg < 4 ? sm.P : sm.v);
        } else {
            const int tid2 = tid - 256;
            const int cq2 = tid2 & 31;
            const int rg  = tid2 >> 5;        // 0..7
            col = cq2 * 2;
            AT  = sm.avoT;
            r0  = rg * 4;
            strideA = ST_T32;
            Wg  = W1 + 128 * 64;
            dst = sm.X;
        }
#pragma unroll 4
        for (int k = 0; k < 128; k++) {
            const float2 wv = *reinterpret_cast<const float2*>(Wg + k * 64 + col);
            const ulonglong2 A = *reinterpret_cast<const ulonglong2*>(&AT[k * strideA + r0]);
            const u64 wp0 = pack2(wv.x, wv.x);
            const u64 wp1 = pack2(wv.y, wv.y);
            a00 = fma2(A.x, wp0, a00);
            a01 = fma2(A.y, wp0, a01);
            a10 = fma2(A.x, wp1, a10);
            a11 = fma2(A.y, wp1, a11);
        }
        float x0, x1, x2, x3, y0, y1, y2, y3;
        unpack2(a00, x0, x1); unpack2(a01, x2, x3);
        unpack2(a10, y0, y1); unpack2(a11, y2, y3);
        *reinterpret_cast<float2*>(&dst[(r0 + 0) * ST_PX + col]) = make_float2(x0, y0);
        *reinterpret_cast<float2*>(&dst[(r0 + 1) * ST_PX + col]) = make_float2(x1, y1);
        *reinterpret_cast<float2*>(&dst[(r0 + 2) * ST_PX + col]) = make_float2(x2, y2);
        *reinterpret_cast<float2*>(&dst[(r0 + 3) * ST_PX + col]) = make_float2(x3, y3);
    }
    __syncthreads();

    // ============ Stage 5: u = w @ P + wo @ X ============
    {
        const int i = tid >> 5;
        const int c = (tid & 31) * 2;
        float acc0 = 0.f, acc1 = 0.f;
#pragma unroll
        for (int j = 0; j < 16; j++) {
            const float wv = sm.w[i * 16 + j];
            const float2 p = *reinterpret_cast<const float2*>(&sm.P[j * ST_PX + c]);
            acc0 = fmaf(wv, p.x, acc0);
            acc1 = fmaf(wv, p.y, acc1);
        }
#pragma unroll
        for (int m = 0; m < 32; m++) {
            const float wv = sm.wo[i * 32 + m];
            const float2 x = *reinterpret_cast<const float2*>(&sm.X[m * ST_PX + c]);
            acc0 = fmaf(wv, x.x, acc0);
            acc1 = fmaf(wv, x.y, acc1);
        }
        *reinterpret_cast<float2*>(&sm.u[i * ST_PX + c]) = make_float2(acc0, acc1);
    }
    __syncthreads();

    // ============ Stage 6: final value ============
    {
        const int p = tid >> 1, h = tid & 1;
        const int i = p >> 4, j = p & 15;
        const float wt = sm.w[i * 16 + j];
        float acc = 0.f;
        const int d0 = h * 32;
#pragma unroll 8
        for (int d = d0; d < d0 + 32; d++) {
            float hh = fmaf(wt, sm.v[j * ST_PX + d], sm.u[i * ST_PX + d]);
            hh = (hh > 0.f) ? hh : 0.01f * hh;
            acc = fmaf(hh, sm.w2[d], acc);
        }
        acc += __shfl_xor_sync(0xffffffffu, acc, 1);
        if (h == 0) out_value[(size_t)b * 256 + p] = acc;
    }
}

extern "C" void kernel_launch(void* const* d_in, const int* in_sizes, int n_in,
                              void* d_out, int out_size) {
    const float* states    = (const float*)d_in[0];
    const float* policies  = (const float*)d_in[1];
    const float* actions   = (const float*)d_in[2];
    const float* states_o  = (const float*)d_in[3];
    const float* actions_o = (const float*)d_in[4];
    const float* Wk  = (const float*)d_in[5];
    const float* Wq  = (const float*)d_in[6];
    const float* Wv  = (const float*)d_in[7];
    const float* Wko = (const float*)d_in[8];
    const float* Wqo = (const float*)d_in[9];
    const float* Wvo = (const float*)d_in[10];
    const float* W1  = (const float*)d_in[11];
    const float* W2  = (const float*)d_in[12];

    float* out       = (float*)d_out;
    float* out_value = out;                    // [B,N,N,1]
    float* out_w     = out + BB * 256;         // [B,N,N]
    float* out_wo    = out + 2 * BB * 256;     // [B,N,M,1]

    cudaFuncSetAttribute(critic_kernel,
                         cudaFuncAttributeMaxDynamicSharedMemorySize,
                         (int)sizeof(Smem));

    critic_kernel<<<BB, 512, sizeof(Smem)>>>(states, policies, actions,
                                             states_o, actions_o,
                                             Wk, Wq, Wv, Wko, Wqo, Wvo, W1, W2,
                                             out_value, out_w, out_wo);
}

// round 4
// speedup vs baseline: 2.0574x; 1.0072x over previous
#include <cuda_runtime.h>

#define BB 128
typedef unsigned long long u64;

__device__ __forceinline__ u64 pack2(float x, float y){
    u64 r; asm("mov.b64 %0,{%1,%2};" : "=l"(r) : "f"(x), "f"(y)); return r;
}
__device__ __forceinline__ void unpack2(u64 a, float& x, float& y){
    asm("mov.b64 {%0,%1},%2;" : "=f"(x), "=f"(y) : "l"(a));
}
__device__ __forceinline__ u64 fma2(u64 a, u64 b, u64 c){
    u64 d; asm("fma.rn.f32x2 %0,%1,%2,%3;" : "=l"(d) : "l"(a), "l"(b), "l"(c)); return d;
}
__device__ __forceinline__ float fast_tanh(float x){
    float e = __expf(2.0f * x);
    return 1.0f - __fdividef(2.0f, e + 1.0f);
}

#define ST_T16 20   // [K][16] transposed tiles (floats)
#define ST_T32 36   // [K][32] transposed tiles
#define ST_RM  132  // row-major [16][128] tile
#define ST_PX  66   // row-major [R][64] tiles (P, X, u, v)

struct Smem {
    float sT    [128 * ST_T16];  // states^T
    float oaoT  [136 * ST_T32];  // [states_o | actions_o]^T
    float act   [16 * 8];
    float pol   [16 * 8];
    float kkT   [128 * ST_T16];
    float qqT   [128 * ST_T16];
    float qoT   [128 * ST_T16];
    float t     [16 * ST_RM];    // states @ Wv[:128], row-major
    float koT   [128 * ST_T32];
    float avoT  [128 * ST_T32];  // tanh(oao @ Wvo), transposed
    float avactT[128 * ST_T16];
    float deltaT[128 * ST_T16];
    float w     [256];
    float wo    [512];
    float P     [16 * ST_PX];    // avact @ W1a
    float X     [32 * ST_PX];    // avo   @ W1b
    float u     [16 * ST_PX];
    float v     [16 * ST_PX];    // delta @ W1a
    float w2    [64];
};

__global__ __launch_bounds__(512, 1)
void critic_kernel(const float* __restrict__ states,
                   const float* __restrict__ policies,
                   const float* __restrict__ actions,
                   const float* __restrict__ states_o,
                   const float* __restrict__ actions_o,
                   const float* __restrict__ Wk,  const float* __restrict__ Wq,
                   const float* __restrict__ Wv,  const float* __restrict__ Wko,
                   const float* __restrict__ Wqo, const float* __restrict__ Wvo,
                   const float* __restrict__ W1,  const float* __restrict__ W2,
                   float* __restrict__ out_value,
                   float* __restrict__ out_w,
                   float* __restrict__ out_wo)
{
    extern __shared__ unsigned char smem_raw[];
    Smem& sm = *reinterpret_cast<Smem*>(smem_raw);

    const int b   = blockIdx.x;
    const int tid = threadIdx.x;

    // ============ Stage 0: load + transpose inputs ============
    {
        const int k  = tid & 127;
        const int g  = tid >> 7;       // 0..3
        const int r0 = g * 4;
        const float* S = states + (size_t)b * 16 * 128;
        {
            float a0 = S[(r0 + 0) * 128 + k];
            float a1 = S[(r0 + 1) * 128 + k];
            float a2 = S[(r0 + 2) * 128 + k];
            float a3 = S[(r0 + 3) * 128 + k];
            *reinterpret_cast<float4*>(&sm.sT[k * ST_T16 + r0]) = make_float4(a0, a1, a2, a3);
        }
        const float* SO = states_o + (size_t)b * 32 * 128;
#pragma unroll
        for (int h = 0; h < 32; h += 16) {
            float a0 = SO[(r0 + h + 0) * 128 + k];
            float a1 = SO[(r0 + h + 1) * 128 + k];
            float a2 = SO[(r0 + h + 2) * 128 + k];
            float a3 = SO[(r0 + h + 3) * 128 + k];
            *reinterpret_cast<float4*>(&sm.oaoT[k * ST_T32 + r0 + h]) = make_float4(a0, a1, a2, a3);
        }
        if (tid < 256) {
            int kk8 = tid >> 5, m = tid & 31;
            sm.oaoT[(128 + kk8) * ST_T32 + m] = actions_o[(size_t)b * 32 * 8 + m * 8 + kk8];
        }
        if (tid < 128) {
            int r = tid >> 3, c = tid & 7;
            sm.act[r * 8 + c] = actions[(size_t)b * 16 * 8 + r * 8 + c];
            sm.pol[r * 8 + c] = policies[(size_t)b * 16 * 8 + r * 8 + c];
        }
        if (tid < 64) sm.w2[tid] = W2[tid];
    }
    __syncthreads();

    // ============ Stage 1: warp-specialized projection GEMMs (k-skewed) ============
    if (tid < 256) {
        // warps 0-7: states projections (Wk | Wq | Wqo | Wv[:128]); 512 cols x 16 rows
        const int lane = tid & 31;
        const int warp = tid >> 5;        // 0..7
        const int mat  = warp & 3;
        const int r0   = (warp >> 2) * 8; // 0 or 8
        const int col  = lane * 4;
        const int koff = warp * 16;       // per-warp k start: de-sync LDG bursts
        const float* Wm = (mat == 0 ? Wk : mat == 1 ? Wq : mat == 2 ? Wqo : Wv) + col;

        u64 acc[4][4];
#pragma unroll
        for (int j = 0; j < 4; j++)
#pragma unroll
            for (int p = 0; p < 4; p++) acc[j][p] = 0ull;

        auto step = [&](int k) {
            const float4 w4 = *reinterpret_cast<const float4*>(Wm + k * 128);
            const ulonglong2 A0 = *reinterpret_cast<const ulonglong2*>(&sm.sT[k * ST_T16 + r0]);
            const ulonglong2 A1 = *reinterpret_cast<const ulonglong2*>(&sm.sT[k * ST_T16 + r0 + 4]);
            const u64 wp0 = pack2(w4.x, w4.x);
            const u64 wp1 = pack2(w4.y, w4.y);
            const u64 wp2 = pack2(w4.z, w4.z);
            const u64 wp3 = pack2(w4.w, w4.w);
            acc[0][0] = fma2(A0.x, wp0, acc[0][0]);
            acc[0][1] = fma2(A0.y, wp0, acc[0][1]);
            acc[0][2] = fma2(A1.x, wp0, acc[0][2]);
            acc[0][3] = fma2(A1.y, wp0, acc[0][3]);
            acc[1][0] = fma2(A0.x, wp1, acc[1][0]);
            acc[1][1] = fma2(A0.y, wp1, acc[1][1]);
            acc[1][2] = fma2(A1.x, wp1, acc[1][2]);
            acc[1][3] = fma2(A1.y, wp1, acc[1][3]);
            acc[2][0] = fma2(A0.x, wp2, acc[2][0]);
            acc[2][1] = fma2(A0.y, wp2, acc[2][1]);
            acc[2][2] = fma2(A1.x, wp2, acc[2][2]);
            acc[2][3] = fma2(A1.y, wp2, acc[2][3]);
            acc[3][0] = fma2(A0.x, wp3, acc[3][0]);
            acc[3][1] = fma2(A0.y, wp3, acc[3][1]);
            acc[3][2] = fma2(A1.x, wp3, acc[3][2]);
            acc[3][3] = fma2(A1.y, wp3, acc[3][3]);
        };
#pragma unroll 4
        for (int k = koff; k < 128; k++) step(k);
#pragma unroll 4
        for (int k = 0; k < koff; k++) step(k);

        if (mat < 3) {
            float* oT = (mat == 0 ? sm.kkT : mat == 1 ? sm.qqT : sm.qoT);
#pragma unroll
            for (int j = 0; j < 4; j++) {
                float* d = oT + (col + j) * ST_T16 + r0;
                ulonglong2 s0 = {acc[j][0], acc[j][1]};
                ulonglong2 s1 = {acc[j][2], acc[j][3]};
                *reinterpret_cast<ulonglong2*>(d)     = s0;
                *reinterpret_cast<ulonglong2*>(d + 4) = s1;
            }
        } else {
#pragma unroll
            for (int p = 0; p < 4; p++) {
                float x0, y0, x1, y1, x2, y2, x3, y3;
                unpack2(acc[0][p], x0, y0);
                unpack2(acc[1][p], x1, y1);
                unpack2(acc[2][p], x2, y2);
                unpack2(acc[3][p], x3, y3);
                *reinterpret_cast<float4*>(&sm.t[(r0 + 2 * p + 0) * ST_RM + col]) = make_float4(x0, x1, x2, x3);
                *reinterpret_cast<float4*>(&sm.t[(r0 + 2 * p + 1) * ST_RM + col]) = make_float4(y0, y1, y2, y3);
            }
        }
    } else {
        // warps 8-15: other-agent projections (Wko | Wvo); 256 cols x 32 rows
        const int tid2 = tid - 256;
        const int lane = tid2 & 31;
        const int wrp  = tid2 >> 5;      // 0..7
        const int mat  = wrp & 1;        // 0 = Wko, 1 = Wvo
        const int r0   = (wrp >> 1) * 8; // 0,8,16,24
        const int col  = lane * 4;
        const int koff = (wrp * 16 + 8) & 127;  // offset from warps 0-7 too
        const float* Wm = (mat ? Wvo : Wko) + col;

        u64 acc[4][4];
#pragma unroll
        for (int j = 0; j < 4; j++)
#pragma unroll
            for (int p = 0; p < 4; p++) acc[j][p] = 0ull;

        auto step = [&](int k) {
            const float4 w4 = *reinterpret_cast<const float4*>(Wm + k * 128);
            const ulonglong2 A0 = *reinterpret_cast<const ulonglong2*>(&sm.oaoT[k * ST_T32 + r0]);
            const ulonglong2 A1 = *reinterpret_cast<const ulonglong2*>(&sm.oaoT[k * ST_T32 + r0 + 4]);
            const u64 wp0 = pack2(w4.x, w4.x);
            const u64 wp1 = pack2(w4.y, w4.y);
            const u64 wp2 = pack2(w4.z, w4.z);
            const u64 wp3 = pack2(w4.w, w4.w);
            acc[0][0] = fma2(A0.x, wp0, acc[0][0]);
            acc[0][1] = fma2(A0.y, wp0, acc[0][1]);
            acc[0][2] = fma2(A1.x, wp0, acc[0][2]);
            acc[0][3] = fma2(A1.y, wp0, acc[0][3]);
            acc[1][0] = fma2(A0.x, wp1, acc[1][0]);
            acc[1][1] = fma2(A0.y, wp1, acc[1][1]);
            acc[1][2] = fma2(A1.x, wp1, acc[1][2]);
            acc[1][3] = fma2(A1.y, wp1, acc[1][3]);
            acc[2][0] = fma2(A0.x, wp2, acc[2][0]);
            acc[2][1] = fma2(A0.y, wp2, acc[2][1]);
            acc[2][2] = fma2(A1.x, wp2, acc[2][2]);
            acc[2][3] = fma2(A1.y, wp2, acc[2][3]);
            acc[3][0] = fma2(A0.x, wp3, acc[3][0]);
            acc[3][1] = fma2(A0.y, wp3, acc[3][1]);
            acc[3][2] = fma2(A1.x, wp3, acc[3][2]);
            acc[3][3] = fma2(A1.y, wp3, acc[3][3]);
        };
#pragma unroll 4
        for (int k = koff; k < 128; k++) step(k);
#pragma unroll 4
        for (int k = 0; k < koff; k++) step(k);

        if (mat == 0) {
#pragma unroll
            for (int j = 0; j < 4; j++) {
                float* d = sm.koT + (col + j) * ST_T32 + r0;
                ulonglong2 s0 = {acc[j][0], acc[j][1]};
                ulonglong2 s1 = {acc[j][2], acc[j][3]};
                *reinterpret_cast<ulonglong2*>(d)     = s0;
                *reinterpret_cast<ulonglong2*>(d + 4) = s1;
            }
        } else {
            // Wvo tail: K 128..135 (actions_other)
#pragma unroll
            for (int k = 128; k < 136; k++) step(k);
#pragma unroll
            for (int j = 0; j < 4; j++) {
                float t0, t1, t2, t3, t4, t5, t6, t7;
                unpack2(acc[j][0], t0, t1);
                unpack2(acc[j][1], t2, t3);
                unpack2(acc[j][2], t4, t5);
                unpack2(acc[j][3], t6, t7);
                float* d = sm.avoT + (col + j) * ST_T32 + r0;
                *reinterpret_cast<float4*>(d)     = make_float4(fast_tanh(t0), fast_tanh(t1), fast_tanh(t2), fast_tanh(t3));
                *reinterpret_cast<float4*>(d + 4) = make_float4(fast_tanh(t4), fast_tanh(t5), fast_tanh(t6), fast_tanh(t7));
            }
        }
    }
    __syncthreads();

    // ============ Stage 2: avactT/deltaT tails + attention scores ============
    {
        const int g  = tid >> 7;    // 0..3
        const int c  = tid & 127;
        const int r0 = g * 4;
        float aa[4], ap[4];
#pragma unroll
        for (int i = 0; i < 4; i++) {
            float tv = sm.t[(r0 + i) * ST_RM + c];
            aa[i] = tv; ap[i] = tv;
        }
#pragma unroll
        for (int k = 0; k < 8; k++) {
            float wv = Wv[(128 + k) * 128 + c];
#pragma unroll
            for (int i = 0; i < 4; i++) {
                aa[i] = fmaf(sm.act[(r0 + i) * 8 + k], wv, aa[i]);
                ap[i] = fmaf(sm.pol[(r0 + i) * 8 + k], wv, ap[i]);
            }
        }
        float ta[4], dl[4];
#pragma unroll
        for (int i = 0; i < 4; i++) {
            ta[i] = fast_tanh(aa[i]);
            dl[i] = fast_tanh(ap[i]) - ta[i];
        }
        *reinterpret_cast<float4*>(&sm.avactT[c * ST_T16 + r0]) = make_float4(ta[0], ta[1], ta[2], ta[3]);
        *reinterpret_cast<float4*>(&sm.deltaT[c * ST_T16 + r0]) = make_float4(dl[0], dl[1], dl[2], dl[3]);
    }
    const float scale = 0.08838834764831845f;  // 1/sqrt(128)
    {
        const int i = tid >> 5, m = tid & 31;
        float a0 = 0.f, a1 = 0.f, a2 = 0.f, a3 = 0.f;
#pragma unroll
        for (int k = 0; k < 128; k += 4) {
            a0 = fmaf(sm.qoT[(k + 0) * ST_T16 + i], sm.koT[(k + 0) * ST_T32 + m], a0);
            a1 = fmaf(sm.qoT[(k + 1) * ST_T16 + i], sm.koT[(k + 1) * ST_T32 + m], a1);
            a2 = fmaf(sm.qoT[(k + 2) * ST_T16 + i], sm.koT[(k + 2) * ST_T32 + m], a2);
            a3 = fmaf(sm.qoT[(k + 3) * ST_T16 + i], sm.koT[(k + 3) * ST_T32 + m], a3);
        }
        sm.wo[i * 32 + m] = ((a0 + a1) + (a2 + a3)) * scale;
    }
    if (tid < 256) {
        const int i = tid >> 4, j = tid & 15;
        float a0 = 0.f, a1 = 0.f, a2 = 0.f, a3 = 0.f;
#pragma unroll
        for (int k = 0; k < 128; k += 4) {
            a0 = fmaf(sm.qqT[(k + 0) * ST_T16 + i], sm.kkT[(k + 0) * ST_T16 + j], a0);
            a1 = fmaf(sm.qqT[(k + 1) * ST_T16 + i], sm.kkT[(k + 1) * ST_T16 + j], a1);
            a2 = fmaf(sm.qqT[(k + 2) * ST_T16 + i], sm.kkT[(k + 2) * ST_T16 + j], a2);
            a3 = fmaf(sm.qqT[(k + 3) * ST_T16 + i], sm.kkT[(k + 3) * ST_T16 + j], a3);
        }
        sm.w[i * 16 + j] = ((a0 + a1) + (a2 + a3)) * scale;
    }
    __syncthreads();

    // ============ Stage 3: softmaxes (few threads) + P/v/X GEMMs (all) ============
    if (tid < 16) {
        const int i = tid;
        float mx = -1e30f;
#pragma unroll
        for (int j = 0; j < 16; j++) mx = fmaxf(mx, sm.w[i * 16 + j]);
        float s = 0.f, e[16];
#pragma unroll
        for (int j = 0; j < 16; j++) { e[j] = __expf(sm.w[i * 16 + j] - mx); s += e[j]; }
        const float inv = __fdividef(1.f, s);
#pragma unroll
        for (int j = 0; j < 16; j++) {
            float p = e[j] * inv;
            sm.w[i * 16 + j] = p;
            out_w[(size_t)b * 256 + i * 16 + j] = p;
        }
    } else if (tid < 48) {
        const int m = tid - 16;
        float mx = -1e30f;
#pragma unroll
        for (int i = 0; i < 16; i++) mx = fmaxf(mx, sm.wo[i * 32 + m]);
        float s = 0.f, e[16];
#pragma unroll
        for (int i = 0; i < 16; i++) { e[i] = __expf(sm.wo[i * 32 + m] - mx); s += e[i]; }
        const float inv = __fdividef(1.f, s);
#pragma unroll
        for (int i = 0; i < 16; i++) {
            float p = e[i] * inv;
            sm.wo[i * 32 + m] = p;
            out_wo[(size_t)b * 512 + i * 32 + m] = p;
        }
    }
    // P = avact @ W1a, v = delta @ W1a, X = avo @ W1b (independent of softmax)
    {
        u64 a00 = 0ull, a01 = 0ull, a10 = 0ull, a11 = 0ull;
        const float* AT;
        const float* Wg;
        float* dst;
        int r0, strideA, col;
        if (tid < 256) {
            const int cq2 = tid & 31;
            const int rg  = tid >> 5;         // 0..7
            col = cq2 * 2;
            AT  = (rg < 4 ? sm.avactT : sm.deltaT);
            r0  = (rg & 3) * 4;
            strideA = ST_T16;
            Wg  = W1;
            dst = (rg < 4 ? sm.P : sm.v);
        } else {
            const int tid2 = tid - 256;
            const int cq2 = tid2 & 31;
            const int rg  = tid2 >> 5;        // 0..7
            col = cq2 * 2;
            AT  = sm.avoT;
            r0  = rg * 4;
            strideA = ST_T32;
            Wg  = W1 + 128 * 64;
            dst = sm.X;
        }
        const int koff = ((tid >> 5) & 7) * 16;   // per-warp k skew
        auto step = [&](int k) {
            const float2 wv = *reinterpret_cast<const float2*>(Wg + k * 64 + col);
            const ulonglong2 A = *reinterpret_cast<const ulonglong2*>(&AT[k * strideA + r0]);
            const u64 wp0 = pack2(wv.x, wv.x);
            const u64 wp1 = pack2(wv.y, wv.y);
            a00 = fma2(A.x, wp0, a00);
            a01 = fma2(A.y, wp0, a01);
            a10 = fma2(A.x, wp1, a10);
            a11 = fma2(A.y, wp1, a11);
        };
#pragma unroll 4
        for (int k = koff; k < 128; k++) step(k);
#pragma unroll 4
        for (int k = 0; k < koff; k++) step(k);

        float x0, x1, x2, x3, y0, y1, y2, y3;
        unpack2(a00, x0, x1); unpack2(a01, x2, x3);
        unpack2(a10, y0, y1); unpack2(a11, y2, y3);
        *reinterpret_cast<float2*>(&dst[(r0 + 0) * ST_PX + col]) = make_float2(x0, y0);
        *reinterpret_cast<float2*>(&dst[(r0 + 1) * ST_PX + col]) = make_float2(x1, y1);
        *reinterpret_cast<float2*>(&dst[(r0 + 2) * ST_PX + col]) = make_float2(x2, y2);
        *reinterpret_cast<float2*>(&dst[(r0 + 3) * ST_PX + col]) = make_float2(x3, y3);
    }
    __syncthreads();

    // ============ Stage 5: u = w @ P + wo @ X ============
    {
        const int i = tid >> 5;
        const int c = (tid & 31) * 2;
        float acc0 = 0.f, acc1 = 0.f, bcc0 = 0.f, bcc1 = 0.f;
#pragma unroll
        for (int j = 0; j < 16; j += 2) {
            const float wv0 = sm.w[i * 16 + j];
            const float wv1 = sm.w[i * 16 + j + 1];
            const float2 p0 = *reinterpret_cast<const float2*>(&sm.P[j * ST_PX + c]);
            const float2 p1 = *reinterpret_cast<const float2*>(&sm.P[(j + 1) * ST_PX + c]);
            acc0 = fmaf(wv0, p0.x, acc0);
            acc1 = fmaf(wv0, p0.y, acc1);
            bcc0 = fmaf(wv1, p1.x, bcc0);
            bcc1 = fmaf(wv1, p1.y, bcc1);
        }
#pragma unroll
        for (int m = 0; m < 32; m += 2) {
            const float wv0 = sm.wo[i * 32 + m];
            const float wv1 = sm.wo[i * 32 + m + 1];
            const float2 x0 = *reinterpret_cast<const float2*>(&sm.X[m * ST_PX + c]);
            const float2 x1 = *reinterpret_cast<const float2*>(&sm.X[(m + 1) * ST_PX + c]);
            acc0 = fmaf(wv0, x0.x, acc0);
            acc1 = fmaf(wv0, x0.y, acc1);
            bcc0 = fmaf(wv1, x1.x, bcc0);
            bcc1 = fmaf(wv1, x1.y, bcc1);
        }
        *reinterpret_cast<float2*>(&sm.u[i * ST_PX + c]) = make_float2(acc0 + bcc0, acc1 + bcc1);
    }
    __syncthreads();

    // ============ Stage 6: final value ============
    {
        const int p = tid >> 1, h = tid & 1;
        const int i = p >> 4, j = p & 15;
        const float wt = sm.w[i * 16 + j];
        float acc0 = 0.f, acc1 = 0.f;
        const int d0 = h * 32;
#pragma unroll
        for (int d = d0; d < d0 + 32; d += 2) {
            float h0 = fmaf(wt, sm.v[j * ST_PX + d],     sm.u[i * ST_PX + d]);
            float h1 = fmaf(wt, sm.v[j * ST_PX + d + 1], sm.u[i * ST_PX + d + 1]);
            h0 = fmaxf(h0, 0.01f * h0);
            h1 = fmaxf(h1, 0.01f * h1);
            acc0 = fmaf(h0, sm.w2[d],     acc0);
            acc1 = fmaf(h1, sm.w2[d + 1], acc1);
        }
        float acc = acc0 + acc1;
        acc += __shfl_xor_sync(0xffffffffu, acc, 1);
        if (h == 0) out_value[(size_t)b * 256 + p] = acc;
    }
}

extern "C" void kernel_launch(void* const* d_in, const int* in_sizes, int n_in,
                              void* d_out, int out_size) {
    const float* states    = (const float*)d_in[0];
    const float* policies  = (const float*)d_in[1];
    const float* actions   = (const float*)d_in[2];
    const float* states_o  = (const float*)d_in[3];
    const float* actions_o = (const float*)d_in[4];
    const float* Wk  = (const float*)d_in[5];
    const float* Wq  = (const float*)d_in[6];
    const float* Wv  = (const float*)d_in[7];
    const float* Wko = (const float*)d_in[8];
    const float* Wqo = (const float*)d_in[9];
    const float* Wvo = (const float*)d_in[10];
    const float* W1  = (const float*)d_in[11];
    const float* W2  = (const float*)d_in[12];

    float* out       = (float*)d_out;
    float* out_value = out;                    // [B,N,N,1]
    float* out_w     = out + BB * 256;         // [B,N,N]
    float* out_wo    = out + 2 * BB * 256;     // [B,N,M,1]

    cudaFuncSetAttribute(critic_kernel,
                         cudaFuncAttributeMaxDynamicSharedMemorySize,
                         (int)sizeof(Smem));

    critic_kernel<<<BB, 512, sizeof(Smem)>>>(states, policies, actions,
                                             states_o, actions_o,
                                             Wk, Wq, Wv, Wko, Wqo, Wvo, W1, W2,
                                             out_value, out_w, out_wo);
}